// round 1
// baseline (speedup 1.0000x reference)
#include <cuda_runtime.h>
#include <cstdint>

// Problem constants
#define NB   32
#define NAC  5
#define NC   20
#define NH   76
#define NW   76
#define MAXT 50
#define CELLS_PER_IMG (NAC * NH * NW)   // 28880
#define PLANE (NH * NW)                 // 5776
#define BLK2  256
#define GX2   113                        // ceil(28880/256)
#define NPART (GX2 * NB)                 // 3616

#define SIL_NUM 3.0f   // iou > 0.6  <=>  8*carea > 3*(pa+ga)
#define SIL_DEN 8.0f

// -------- device scratch (no allocations allowed) --------
__device__ int   g_cnt[NB];
__device__ float g_tf[NB][MAXT][9];   // gx,gy,gw,gh, tx,ty,tw,th, tconf
__device__ int   g_ti[NB][MAXT][2];   // cell (image-local), cls
__device__ float g_partial[NPART];

__device__ __forceinline__ float sigf(float v) {
    return 1.0f / (1.0f + __expf(-v));
}

// ---------------- Kernel 1: per-target preprocessing ----------------
__global__ void k_targets(const float* __restrict__ out,
                          const float* __restrict__ tgt,
                          const float* __restrict__ anch) {
    int b = blockIdx.x;
    int t = threadIdx.x;           // blockDim = 64
    __shared__ float s_aw[NAC], s_ah[NAC];
    __shared__ int vflag[MAXT];
    __shared__ int slot[MAXT];

    if (t < NAC) { s_aw[t] = anch[2 * t]; s_ah[t] = anch[2 * t + 1]; }
    __syncthreads();

    bool valid = false;
    float gx = 0, gy = 0, gw = 0, gh = 0, tx = 0, ty = 0, tw = 0, th = 0, tconf = 0;
    int cell = -1, cls = 0;

    if (t < MAXT) {
        const float* tp = tgt + (b * MAXT + t) * 5;
        float f0 = tp[0], f1 = tp[1], f2 = tp[2], f3 = tp[3], f4 = tp[4];
        valid = (f1 != 0.0f);
        vflag[t] = valid ? 1 : 0;
        if (valid) {
            gx = f1 * (float)NW; gy = f2 * (float)NH;
            gw = f3 * (float)NW; gh = f4 * (float)NH;
            cls = (int)f0;
            // best anchor by IoU of (0,0,gw,gh) vs (0,0,aw,ah)
            float best = -1.0f; int bn = 0;
            float garea = gw * gh;
            #pragma unroll
            for (int a = 0; a < NAC; a++) {
                float cw = fminf(gw, s_aw[a]);
                float ch = fminf(gh, s_ah[a]);
                float ca = cw * ch;
                float iou = ca / (garea + s_aw[a] * s_ah[a] - ca);
                if (iou > best) { best = iou; bn = a; }
            }
            int gi = min(max((int)gx, 0), NW - 1);
            int gj = min(max((int)gy, 0), NH - 1);
            cell = (bn * NH + gj) * NW + gi;
            tx = gx - (float)gi;
            ty = gy - (float)gj;
            tw = logf(gw / s_aw[bn]);
            th = logf(gh / s_ah[bn]);
            // pred box at (b, bn, gj, gi)
            const float* p = out + (size_t)(b * (NAC * (5 + NC)) + bn * (5 + NC)) * PLANE
                                 + gj * NW + gi;
            float px = sigf(p[0]) + (float)gi;
            float py = sigf(p[PLANE]) + (float)gj;
            float pw = expf(p[2 * PLANE]) * s_aw[bn];
            float ph = expf(p[3 * PLANE]) * s_ah[bn];
            float uw = fmaxf(gx + 0.5f * gw, px + 0.5f * pw) - fminf(gx - 0.5f * gw, px - 0.5f * pw);
            float uh = fmaxf(gy + 0.5f * gh, py + 0.5f * ph) - fminf(gy - 0.5f * gh, py - 0.5f * ph);
            float cw = gw + pw - uw;
            float ch = gh + ph - uh;
            float ca = (cw <= 0.0f || ch <= 0.0f) ? 0.0f : cw * ch;
            tconf = ca / (garea + pw * ph - ca);
        }
    } else if (t < 64) {
        // nothing
    }
    __syncthreads();
    if (t == 0) {
        int c = 0;
        for (int k = 0; k < MAXT; k++) slot[k] = vflag[k] ? c++ : -1;
        g_cnt[b] = c;
    }
    __syncthreads();
    if (t < MAXT && valid) {
        int s = slot[t];
        float* dst = g_tf[b][s];
        dst[0] = gx; dst[1] = gy; dst[2] = gw; dst[3] = gh;
        dst[4] = tx; dst[5] = ty; dst[6] = tw; dst[7] = th; dst[8] = tconf;
        g_ti[b][s][0] = cell;
        g_ti[b][s][1] = cls;
    }
}

// ---------------- Kernel 2: per-cell loss ----------------
__global__ __launch_bounds__(BLK2) void k_main(const float* __restrict__ out,
                                               const float* __restrict__ anch) {
    int b   = blockIdx.y;
    int tid = threadIdx.x;
    int cellInImg = blockIdx.x * BLK2 + tid;

    __shared__ float s_f[MAXT][9];
    __shared__ int   s_cell[MAXT];
    __shared__ int   s_cls[MAXT];
    __shared__ float s_aw[NAC], s_ah[NAC];
    __shared__ float red[BLK2];

    int cnt = g_cnt[b];
    if (tid < NAC) { s_aw[tid] = anch[2 * tid]; s_ah[tid] = anch[2 * tid + 1]; }
    if (tid < cnt) {
        #pragma unroll
        for (int q = 0; q < 9; q++) s_f[tid][q] = g_tf[b][tid][q];
        s_cell[tid] = g_ti[b][tid][0];
        s_cls[tid]  = g_ti[b][tid][1];
    }
    __syncthreads();

    float loss = 0.0f;
    if (cellInImg < CELLS_PER_IMG) {
        int a   = cellInImg / PLANE;
        int rem = cellInImg - a * PLANE;
        int j   = rem / NW;
        int i   = rem - j * NW;

        const float* p = out + (size_t)(b * (NAC * (5 + NC)) + a * (5 + NC)) * PLANE + rem;
        float o0 = p[0];
        float o1 = p[PLANE];
        float o2 = p[2 * PLANE];
        float o3 = p[3 * PLANE];
        float o4 = p[4 * PLANE];

        float x    = sigf(o0);
        float y    = sigf(o1);
        float conf = sigf(o4);
        float px = x + (float)i;
        float py = y + (float)j;
        float pw = __expf(o2) * s_aw[a];
        float ph = __expf(o3) * s_ah[a];
        float parea = pw * ph;
        float phx = px + 0.5f * pw, plx = px - 0.5f * pw;
        float phy = py + 0.5f * ph, ply = py - 0.5f * ph;

        float noobj = 1.0f;      // NOOBJ_SCALE
        int   tm = -1;
        for (int t = 0; t < cnt; t++) {
            if (s_cell[t] == cellInImg) tm = t;
            float gx = s_f[t][0], gy = s_f[t][1], gw = s_f[t][2], gh = s_f[t][3];
            float uw = fmaxf(phx, gx + 0.5f * gw) - fminf(plx, gx - 0.5f * gw);
            float uh = fmaxf(phy, gy + 0.5f * gh) - fminf(ply, gy - 0.5f * gh);
            float cw = pw + gw - uw;
            float ch = ph + gh - uh;
            if (cw > 0.0f && ch > 0.0f) {
                float ca = cw * ch;
                // iou > 0.6  <=>  8*ca > 3*(parea+garea)
                if (SIL_DEN * ca > SIL_NUM * (parea + gw * gh)) noobj = 0.0f;
            }
        }

        if (tm >= 0) {
            float tx = s_f[tm][4], ty = s_f[tm][5], tw = s_f[tm][6], th = s_f[tm][7];
            float tconf = s_f[tm][8];
            int   cls   = s_cls[tm];
            float dx = x  - tx, dy = y  - ty, dw = o2 - tw, dh = o3 - th;
            loss += 0.5f * (dx * dx + dy * dy + dw * dw + dh * dh);
            float dc = conf - tconf;
            loss += 0.5f * 5.0f * dc * dc;   // OBJ_SCALE
            // cross-entropy over 20 classes
            float lg[NC];
            float mx = -1e30f;
            #pragma unroll
            for (int c = 0; c < NC; c++) {
                lg[c] = p[(5 + c) * PLANE];
                mx = fmaxf(mx, lg[c]);
            }
            float se = 0.0f;
            #pragma unroll
            for (int c = 0; c < NC; c++) se += __expf(lg[c] - mx);
            loss += (logf(se) + mx) - lg[cls];
        } else {
            loss += 0.5f * noobj * conf * conf;
        }
    }

    red[tid] = loss;
    __syncthreads();
    #pragma unroll
    for (int s = BLK2 / 2; s > 0; s >>= 1) {
        if (tid < s) red[tid] += red[tid + s];
        __syncthreads();
    }
    if (tid == 0) g_partial[blockIdx.y * gridDim.x + blockIdx.x] = red[0];
}

// ---------------- Kernel 3: final reduction ----------------
__global__ void k_final(float* __restrict__ outv) {
    __shared__ double red[256];
    int tid = threadIdx.x;
    double acc = 0.0;
    for (int i = tid; i < NPART; i += 256) acc += (double)g_partial[i];
    red[tid] = acc;
    __syncthreads();
    #pragma unroll
    for (int s = 128; s > 0; s >>= 1) {
        if (tid < s) red[tid] += red[tid + s];
        __syncthreads();
    }
    if (tid == 0) outv[0] = (float)(red[0] / (double)NB);
}

extern "C" void kernel_launch(void* const* d_in, const int* in_sizes, int n_in,
                              void* d_out, int out_size) {
    const float* out  = (const float*)d_in[0];
    const float* tgt  = (const float*)d_in[1];
    const float* anch = (const float*)d_in[2];
    float* o = (float*)d_out;

    k_targets<<<NB, 64>>>(out, tgt, anch);
    dim3 g2(GX2, NB);
    k_main<<<g2, BLK2>>>(out, anch);
    k_final<<<1, 256>>>(o);
}